// round 1
// baseline (speedup 1.0000x reference)
#include <cuda_runtime.h>
#include <cstdint>

// Problem constants
#define B_SZ   8
#define K_SZ   2048
#define D_SZ   1024
#define INNER  2048
#define M_SZ   (B_SZ * K_SZ)          // 16384 rows
#define EPS    1e-5f

// ---------------------------------------------------------------------------
// Scratch (device globals: allocation-free, graph-capture safe)
// ---------------------------------------------------------------------------
__device__ float g_H  [(size_t)M_SZ * D_SZ];        //  64 MB  rmsnorm output
__device__ float g_UV [(size_t)M_SZ * 2 * INNER];   // 256 MB  silu(u) | silu(z)
__device__ float g_LAM[(size_t)M_SZ * INNER];       // 128 MB  sigmoid gates
__device__ float g_T  [(size_t)M_SZ * INNER];       // 128 MB  s * silu(z)

// ---------------------------------------------------------------------------
// Kernel 1: RMSNorm.  One block per row (D=1024), 256 threads, float4.
// ---------------------------------------------------------------------------
__global__ void rmsnorm_k(const float* __restrict__ x, const float* __restrict__ wn) {
    size_t row = blockIdx.x;
    int t = threadIdx.x;
    float4 v = ((const float4*)(x + row * D_SZ))[t];
    float ss = v.x*v.x + v.y*v.y + v.z*v.z + v.w*v.w;
    #pragma unroll
    for (int o = 16; o > 0; o >>= 1) ss += __shfl_xor_sync(0xffffffffu, ss, o);

    __shared__ float warpsum[8];
    __shared__ float s_r;
    if ((t & 31) == 0) warpsum[t >> 5] = ss;
    __syncthreads();
    if (t == 0) {
        float tot = 0.f;
        #pragma unroll
        for (int w = 0; w < 8; w++) tot += warpsum[w];
        s_r = rsqrtf(tot * (1.0f / (float)D_SZ) + EPS);
    }
    __syncthreads();
    float r = s_r;
    float4 w = ((const float4*)wn)[t];
    float4 h;
    h.x = v.x * r * w.x; h.y = v.y * r * w.y;
    h.z = v.z * r * w.z; h.w = v.w * r * w.w;
    ((float4*)(g_H + row * D_SZ))[t] = h;
}

// ---------------------------------------------------------------------------
// Kernel 2: SGEMM  C[M,N] = A[M,Kd] * W[N,Kd]^T  (both K-major, "TN")
// 128x128 block tile, BK=16, 256 threads, 8x8 per-thread microtile.
// EPI: 0 = silu, 1 = sigmoid(v + bias[col]), 2 = v + resid[row,col]
// All dims are multiples of the tile sizes -> no bounds checks.
// ---------------------------------------------------------------------------
template<int EPI>
__global__ void __launch_bounds__(256) sgemm_tn(
    const float* __restrict__ A, int lda,
    const float* __restrict__ Bw, int ldb,
    float* __restrict__ C, int ldc,
    int Kd,
    const float* __restrict__ bias,
    const float* __restrict__ resid)
{
    __shared__ float As[16][128];
    __shared__ float Bs[16][128];

    const int bm = blockIdx.y * 128;
    const int bn = blockIdx.x * 128;
    const int t  = threadIdx.x;

    // Global load mapping: each thread loads 2 float4 from A and 2 from B
    const int lr = t >> 2;            // 0..63
    const int lc = (t & 3) << 2;      // 0,4,8,12
    const float* Ag = A  + (size_t)(bm + lr) * lda + lc;
    const float* Bg = Bw + (size_t)(bn + lr) * ldb + lc;

    // Compute mapping
    const int tx = t & 15;            // col group
    const int ty = t >> 4;            // row group

    float acc[8][8];
    #pragma unroll
    for (int i = 0; i < 8; i++)
        #pragma unroll
        for (int j = 0; j < 8; j++) acc[i][j] = 0.f;

    for (int k0 = 0; k0 < Kd; k0 += 16) {
        float4 a0 = *(const float4*)(Ag);
        float4 a1 = *(const float4*)(Ag + (size_t)64 * lda);
        float4 b0 = *(const float4*)(Bg);
        float4 b1 = *(const float4*)(Bg + (size_t)64 * ldb);

        As[lc+0][lr]    = a0.x; As[lc+1][lr]    = a0.y; As[lc+2][lr]    = a0.z; As[lc+3][lr]    = a0.w;
        As[lc+0][lr+64] = a1.x; As[lc+1][lr+64] = a1.y; As[lc+2][lr+64] = a1.z; As[lc+3][lr+64] = a1.w;
        Bs[lc+0][lr]    = b0.x; Bs[lc+1][lr]    = b0.y; Bs[lc+2][lr]    = b0.z; Bs[lc+3][lr]    = b0.w;
        Bs[lc+0][lr+64] = b1.x; Bs[lc+1][lr+64] = b1.y; Bs[lc+2][lr+64] = b1.z; Bs[lc+3][lr+64] = b1.w;
        __syncthreads();

        #pragma unroll
        for (int kk = 0; kk < 16; kk++) {
            float4 a04 = *(const float4*)&As[kk][ty*8];
            float4 a14 = *(const float4*)&As[kk][ty*8+4];
            float4 b04 = *(const float4*)&Bs[kk][tx*8];
            float4 b14 = *(const float4*)&Bs[kk][tx*8+4];
            float a[8] = {a04.x,a04.y,a04.z,a04.w,a14.x,a14.y,a14.z,a14.w};
            float b[8] = {b04.x,b04.y,b04.z,b04.w,b14.x,b14.y,b14.z,b14.w};
            #pragma unroll
            for (int i = 0; i < 8; i++)
                #pragma unroll
                for (int j = 0; j < 8; j++)
                    acc[i][j] = fmaf(a[i], b[j], acc[i][j]);
        }
        __syncthreads();
        Ag += 16;
        Bg += 16;
    }

    #pragma unroll
    for (int i = 0; i < 8; i++) {
        size_t row = (size_t)(bm + ty*8 + i);
        float* crow = C + row * ldc + bn + tx*8;
        float out[8];
        #pragma unroll
        for (int j = 0; j < 8; j++) {
            float v = acc[i][j];
            if (EPI == 0) {                         // silu
                v = v / (1.f + __expf(-v));
            } else if (EPI == 1) {                  // sigmoid(v + bias)
                v += bias[bn + tx*8 + j];
                v = 1.f / (1.f + __expf(-v));
            } else {                                // residual add
                v += resid[row * ldc + bn + tx*8 + j];
            }
            out[j] = v;
        }
        *(float4*)(crow)     = make_float4(out[0], out[1], out[2], out[3]);
        *(float4*)(crow + 4) = make_float4(out[4], out[5], out[6], out[7]);
    }
}

// ---------------------------------------------------------------------------
// Kernel 3: fused sequential scan + s*silu(z).
// One thread per (b, channel i): s_k = lam_k*s_{k-1} + (1-lam_k)*u_k,
// T[b,k,i] = s_k * silu_z[b,k,i].  16384 independent channels.
// Loads are independent of the recurrence -> unroll lets the compiler
// batch them for MLP.
// ---------------------------------------------------------------------------
__global__ void scan_k() {
    int b = blockIdx.x >> 3;                        // 8 blocks of 256 per batch
    int i = ((blockIdx.x & 7) << 8) + threadIdx.x;  // channel 0..2047

    const float* lam = g_LAM + (size_t)b * K_SZ * INNER + i;
    const float* u   = g_UV  + (size_t)b * K_SZ * (2*INNER) + i;          // silu(u)
    const float* sz  = u + INNER;                                          // silu(z)
    float*       tt  = g_T   + (size_t)b * K_SZ * INNER + i;

    float s = 0.f;
    #pragma unroll 8
    for (int k = 0; k < K_SZ; k++) {
        float l  = lam[(size_t)k * INNER];
        float uu = u  [(size_t)k * (2*INNER)];
        float zz = sz [(size_t)k * (2*INNER)];
        s = fmaf(l, s, (1.f - l) * uu);
        tt[(size_t)k * INNER] = s * zz;
    }
}

// ---------------------------------------------------------------------------
// Launch
// ---------------------------------------------------------------------------
extern "C" void kernel_launch(void* const* d_in, const int* in_sizes, int n_in,
                              void* d_out, int out_size) {
    const float* x    = (const float*)d_in[0];   // [8,2048,1024]
    const float* wn   = (const float*)d_in[1];   // [1024]
    const float* Win  = (const float*)d_in[2];   // [4096,1024]
    const float* Wdt  = (const float*)d_in[3];   // [2048,2048]
    const float* bdt  = (const float*)d_in[4];   // [2048]
    const float* Wout = (const float*)d_in[5];   // [1024,2048]
    float* out = (float*)d_out;                  // [8,2048,1024]

    float *H, *UV, *LAM, *T;
    cudaGetSymbolAddress((void**)&H,   g_H);
    cudaGetSymbolAddress((void**)&UV,  g_UV);
    cudaGetSymbolAddress((void**)&LAM, g_LAM);
    cudaGetSymbolAddress((void**)&T,   g_T);

    // 1) RMSNorm -> H
    rmsnorm_k<<<M_SZ, 256>>>(x, wn);

    // 2) UV = silu(H @ Win^T)   [16384 x 4096]
    sgemm_tn<0><<<dim3(2*INNER/128, M_SZ/128), 256>>>(
        H, D_SZ, Win, D_SZ, UV, 2*INNER, D_SZ, nullptr, nullptr);

    // 3) LAM = sigmoid(U @ Wdt^T + b_dt)   [16384 x 2048], U = UV[:, :2048]
    sgemm_tn<1><<<dim3(INNER/128, M_SZ/128), 256>>>(
        UV, 2*INNER, Wdt, INNER, LAM, INNER, INNER, bdt, nullptr);

    // 4) scan + gate -> T
    scan_k<<<(B_SZ * INNER) / 256, 256>>>();

    // 5) out = x + T @ Wout^T   [16384 x 1024]
    sgemm_tn<2><<<dim3(D_SZ/128, M_SZ/128), 256>>>(
        T, INNER, Wout, INNER, out, D_SZ, INNER, nullptr, x);
}

// round 4
// speedup vs baseline: 1.4860x; 1.4860x over previous
#include <cuda_runtime.h>
#include <cstdint>

// ---------------------------------------------------------------------------
// Problem constants
// ---------------------------------------------------------------------------
#define B_SZ   8
#define K_SZ   2048
#define D_SZ   1024
#define INNER  2048
#define M_SZ   (B_SZ * K_SZ)          // 16384 rows
#define EPS    1e-5f

// ---------------------------------------------------------------------------
// Scratch (device globals: allocation-free, graph-capture safe)
// ---------------------------------------------------------------------------
__device__ float g_H  [(size_t)M_SZ * D_SZ];        //  64 MB  rmsnorm output
__device__ float g_UV [(size_t)M_SZ * 2 * INNER];   // 256 MB  silu(u) | silu(z)
__device__ float g_LAM[(size_t)M_SZ * INNER];       // 128 MB  sigmoid gates
__device__ float g_T  [(size_t)M_SZ * INNER];       // 128 MB  s * silu(z)

// ---------------------------------------------------------------------------
// tf32 helpers (plain PTX, sm_80+: works on the sm_100 (non-'a') target)
// ---------------------------------------------------------------------------
__device__ __forceinline__ uint32_t f2tf32(float x) {
    uint32_t y;
    asm("cvt.rna.tf32.f32 %0, %1;" : "=r"(y) : "f"(x));
    return y;
}

// D += A(16x8) * B(8x8), tf32 inputs, f32 accumulate.
#define MMA_TF32(d, a, b0_, b1_)                                          \
    asm volatile(                                                         \
        "mma.sync.aligned.m16n8k8.row.col.f32.tf32.tf32.f32 "             \
        "{%0,%1,%2,%3}, {%4,%5,%6,%7}, {%8,%9}, {%0,%1,%2,%3};"           \
        : "+f"((d)[0]), "+f"((d)[1]), "+f"((d)[2]), "+f"((d)[3])          \
        : "r"((a).x), "r"((a).y), "r"((a).z), "r"((a).w),                 \
          "r"(b0_), "r"(b1_))

// ---------------------------------------------------------------------------
// Fragment-packed smem layouts (all fragment loads = conflict-free lds.128)
//
// A (128 rows x 32 k): per (mrow16 = R/16, kstep = Ck/8) a 16x8 tf32 fragment
// packed thread-major: pos = frag*128 + t*4 + j,
//   t = (R%8)*4 + (Ck%4),  j = ((R%16)/8) + 2*((Ck%8)/4)
// A-fragment reg map (m16n8k8.row): a0=(g,c) a1=(g+8,c) a2=(g,c+4) a3=(g+8,c+4)
//   with g=lane/4, c=lane%4.
//
// B (128 n x 32 k): per (half = n/64, kstep) pack per lane 16 floats
// (8 ntiles x 2 b-regs) split into 4 q-chunks of 128 floats:
//   pos = half*2048 + kstep*512 + q*128 + t*4 + m,
//   t = (n%8)*4 + (k%4),  midx = ((n/8)%8)*2 + (k%4... see below), q = midx/4,
//   m = midx%4.   B-frag (col): b0=(k=lane%4, n=lane/4), b1=(k+4, same n).
// ---------------------------------------------------------------------------
__device__ __forceinline__ int idx_A(int R, int Ck) {
    return ((((R >> 4) << 2) + (Ck >> 3)) << 7)
         + ((((R & 7) << 2) + (Ck & 3)) << 2)
         + ((R >> 3) & 1) + (((Ck >> 2) & 1) << 1);
}
__device__ __forceinline__ int idx_B(int n, int k) {
    int t    = ((n & 7) << 2) + (k & 3);
    int midx = (((n >> 3) & 7) << 1) + ((k >> 2) & 1);
    return ((n >> 6) << 11) + ((k >> 3) << 9) + ((midx >> 2) << 7)
         + (t << 2) + (midx & 3);
}

#define SMEM_FLOATS 16384                   // A0 B0 A1 B1, 4096 floats each
#define SMEM_DYN    (SMEM_FLOATS * 4)       // 64 KB

// ---------------------------------------------------------------------------
// Kernel 1: RMSNorm
// ---------------------------------------------------------------------------
__global__ void rmsnorm_k(const float* __restrict__ x, const float* __restrict__ wn) {
    size_t row = blockIdx.x;
    int t = threadIdx.x;
    float4 v = ((const float4*)(x + row * D_SZ))[t];
    float ss = v.x*v.x + v.y*v.y + v.z*v.z + v.w*v.w;
    #pragma unroll
    for (int o = 16; o > 0; o >>= 1) ss += __shfl_xor_sync(0xffffffffu, ss, o);

    __shared__ float warpsum[8];
    __shared__ float s_r;
    if ((t & 31) == 0) warpsum[t >> 5] = ss;
    __syncthreads();
    if (t == 0) {
        float tot = 0.f;
        #pragma unroll
        for (int w = 0; w < 8; w++) tot += warpsum[w];
        s_r = rsqrtf(tot * (1.0f / (float)D_SZ) + EPS);
    }
    __syncthreads();
    float r = s_r;
    float4 w = ((const float4*)wn)[t];
    float4 h;
    h.x = v.x * r * w.x; h.y = v.y * r * w.y;
    h.z = v.z * r * w.z; h.w = v.w * r * w.w;
    ((float4*)(g_H + row * D_SZ))[t] = h;
}

// ---------------------------------------------------------------------------
// Kernel 2: tf32 mma.sync GEMM   C[M,N] = A[M,Kd] * W[N,Kd]^T
// 128x128 CTA tile, BK=32, 256 threads (8 warps, 4m x 2n, warp tile 32x64),
// double-buffered fragment-packed smem, register prefetch.
// EPI: 0 = silu, 1 = sigmoid(v + bias[col]), 2 = v + resid[row,col]
// ---------------------------------------------------------------------------
template<int EPI>
__global__ void __launch_bounds__(256, 2) gemm_mma(
    const float* __restrict__ A, int lda,
    const float* __restrict__ Bw, int ldb,
    float* __restrict__ C, int ldc,
    int nk,                               // Kd / 32 (even)
    const float* __restrict__ bias,
    const float* __restrict__ resid)
{
    extern __shared__ float smem[];
    float* bufA[2] = { smem,        smem + 8192  };
    float* bufB[2] = { smem + 4096, smem + 12288 };

    const int t    = threadIdx.x;
    const int wid  = t >> 5;
    const int lane = t & 31;
    const int wm   = wid & 3;             // warp row  (0..3)  -> 32 rows each
    const int wn   = wid >> 2;            // warp col  (0..1)  -> 64 cols each
    const int bm   = blockIdx.y * 128;
    const int bn   = blockIdx.x * 128;
    const int lane4 = lane << 2;
    const int wm2   = wm << 1;

    const float* Abase = A  + (size_t)bm * lda;
    const float* Bbase = Bw + (size_t)bn * ldb;
    const int r  = t >> 1;                // 0..127 (row / n)
    const int f0 = (t & 1) << 2;          // float4 index base (0 or 4)

    float c[2][8][4];
    #pragma unroll
    for (int mt = 0; mt < 2; mt++)
        #pragma unroll
        for (int nt = 0; nt < 8; nt++)
            #pragma unroll
            for (int q = 0; q < 4; q++) c[mt][nt][q] = 0.f;

    auto ldg = [&](int kc, float4* a, float4* b) {
        const float* Ap = Abase + (size_t)r * lda + kc * 32 + f0 * 4;
        const float* Bp = Bbase + (size_t)r * ldb + kc * 32 + f0 * 4;
        #pragma unroll
        for (int j = 0; j < 4; j++) {
            a[j] = *(const float4*)(Ap + j * 4);
            b[j] = *(const float4*)(Bp + j * 4);
        }
    };

    auto scatter = [&](int buf, const float4* a, const float4* b) {
        uint32_t* sA = (uint32_t*)bufA[buf];
        uint32_t* sB = (uint32_t*)bufB[buf];
        #pragma unroll
        for (int j = 0; j < 4; j++) {
            int ck = (f0 + j) << 2;
            const float* av = (const float*)&a[j];
            const float* bv = (const float*)&b[j];
            #pragma unroll
            for (int ci = 0; ci < 4; ci++) {
                sA[idx_A(r, ck + ci)] = f2tf32(av[ci]);
                sB[idx_B(r, ck + ci)] = f2tf32(bv[ci]);
            }
        }
    };

    auto compute = [&](int buf) {
        const float* sA = bufA[buf];
        const float* sB = bufB[buf];
        #pragma unroll
        for (int ks = 0; ks < 4; ks++) {
            uint4 af[2];
            #pragma unroll
            for (int mt = 0; mt < 2; mt++)
                af[mt] = *(const uint4*)(sA + (((wm2 + mt) << 2) + ks) * 128 + lane4);
            uint4 bf[4];
            #pragma unroll
            for (int q = 0; q < 4; q++)
                bf[q] = *(const uint4*)(sB + (wn << 11) + (ks << 9) + (q << 7) + lane4);
            const uint32_t* bb = (const uint32_t*)bf;
            #pragma unroll
            for (int mt = 0; mt < 2; mt++)
                #pragma unroll
                for (int nt = 0; nt < 8; nt++)
                    MMA_TF32(c[mt][nt], af[mt], bb[2*nt], bb[2*nt+1]);
        }
    };

    float4 ra[4], rb[4], na[4], nb[4];

    ldg(0, ra, rb);
    scatter(0, ra, rb);
    __syncthreads();

    for (int i = 0; i < nk; i += 2) {
        ldg(i + 1, na, nb);
        compute(0);
        scatter(1, na, nb);
        __syncthreads();

        bool more = (i + 2 < nk);
        if (more) ldg(i + 2, ra, rb);
        compute(1);
        if (more) {
            scatter(0, ra, rb);
            __syncthreads();
        }
    }

    // ---- epilogue ----
    const int g  = lane >> 2;
    const int cp = (lane & 3) << 1;
    #pragma unroll
    for (int mt = 0; mt < 2; mt++) {
        #pragma unroll
        for (int half = 0; half < 2; half++) {
            int grow = bm + wm * 32 + mt * 16 + g + half * 8;
            float* crow = C + (size_t)grow * ldc;
            const float* rrow = (EPI == 2) ? (resid + (size_t)grow * ldc) : nullptr;
            #pragma unroll
            for (int nt = 0; nt < 8; nt++) {
                int col = bn + wn * 64 + nt * 8 + cp;
                float v0 = c[mt][nt][half * 2 + 0];
                float v1 = c[mt][nt][half * 2 + 1];
                if (EPI == 0) {
                    v0 = v0 / (1.f + __expf(-v0));
                    v1 = v1 / (1.f + __expf(-v1));
                } else if (EPI == 1) {
                    float2 bb2 = *(const float2*)(bias + col);
                    v0 = 1.f / (1.f + __expf(-(v0 + bb2.x)));
                    v1 = 1.f / (1.f + __expf(-(v1 + bb2.y)));
                } else {
                    float2 rr = *(const float2*)(rrow + col);
                    v0 += rr.x; v1 += rr.y;
                }
                *(float2*)(crow + col) = make_float2(v0, v1);
            }
        }
    }
}

// ---------------------------------------------------------------------------
// Kernel 3: fused sequential scan + s*silu(z).   128 blocks x 128 threads.
// ---------------------------------------------------------------------------
__global__ void scan_k() {
    int b = blockIdx.x >> 4;                        // 16 blocks of 128 per batch
    int i = ((blockIdx.x & 15) << 7) + threadIdx.x; // channel 0..2047

    const float* lam = g_LAM + (size_t)b * K_SZ * INNER + i;
    const float* u   = g_UV  + (size_t)b * K_SZ * (2*INNER) + i;   // silu(u)
    const float* sz  = u + INNER;                                   // silu(z)
    float*       tt  = g_T   + (size_t)b * K_SZ * INNER + i;

    float s = 0.f;
    #pragma unroll 8
    for (int k = 0; k < K_SZ; k++) {
        float l  = lam[(size_t)k * INNER];
        float uu = u  [(size_t)k * (2*INNER)];
        float zz = sz [(size_t)k * (2*INNER)];
        s = fmaf(l, s, (1.f - l) * uu);
        tt[(size_t)k * INNER] = s * zz;
    }
}

// ---------------------------------------------------------------------------
// Launch
// ---------------------------------------------------------------------------
extern "C" void kernel_launch(void* const* d_in, const int* in_sizes, int n_in,
                              void* d_out, int out_size) {
    const float* x    = (const float*)d_in[0];   // [8,2048,1024]
    const float* wn   = (const float*)d_in[1];   // [1024]
    const float* Win  = (const float*)d_in[2];   // [4096,1024]
    const float* Wdt  = (const float*)d_in[3];   // [2048,2048]
    const float* bdt  = (const float*)d_in[4];   // [2048]
    const float* Wout = (const float*)d_in[5];   // [1024,2048]
    float* out = (float*)d_out;                  // [8,2048,1024]

    float *H, *UV, *LAM, *T;
    cudaGetSymbolAddress((void**)&H,   g_H);
    cudaGetSymbolAddress((void**)&UV,  g_UV);
    cudaGetSymbolAddress((void**)&LAM, g_LAM);
    cudaGetSymbolAddress((void**)&T,   g_T);

    cudaFuncSetAttribute(gemm_mma<0>, cudaFuncAttributeMaxDynamicSharedMemorySize, SMEM_DYN);
    cudaFuncSetAttribute(gemm_mma<1>, cudaFuncAttributeMaxDynamicSharedMemorySize, SMEM_DYN);
    cudaFuncSetAttribute(gemm_mma<2>, cudaFuncAttributeMaxDynamicSharedMemorySize, SMEM_DYN);

    // 1) RMSNorm -> H
    rmsnorm_k<<<M_SZ, 256>>>(x, wn);

    // 2) UV = silu(H @ Win^T)   [16384 x 4096], Kd=1024
    gemm_mma<0><<<dim3(2*INNER/128, M_SZ/128), 256, SMEM_DYN>>>(
        H, D_SZ, Win, D_SZ, UV, 2*INNER, D_SZ/32, nullptr, nullptr);

    // 3) LAM = sigmoid(U @ Wdt^T + b_dt)   [16384 x 2048], Kd=2048
    gemm_mma<1><<<dim3(INNER/128, M_SZ/128), 256, SMEM_DYN>>>(
        UV, 2*INNER, Wdt, INNER, LAM, INNER, INNER/32, bdt, nullptr);

    // 4) scan + gate -> T
    scan_k<<<(B_SZ * INNER) / 128, 128>>>();

    // 5) out = x + T @ Wout^T   [16384 x 1024], Kd=2048
    gemm_mma<2><<<dim3(D_SZ/128, M_SZ/128), 256, SMEM_DYN>>>(
        T, INNER, Wout, INNER, out, D_SZ, INNER/32, nullptr, x);
}